// round 8
// baseline (speedup 1.0000x reference)
#include <cuda_runtime.h>
#include <cuda_fp16.h>
#include <cstdint>

// ============================================================================
// ResAttentionBlock (ptxas target sm_103 rejects tcgen05 -> legacy mma.sync).
// R8: KV GEMMs in int8 IMMA m16n8k32 (2x MACs/instr vs fp16 k16) with
//     activation residual split  y ~= s_row*(a_hi + a_lo/254)  so accuracy is
//     weight-int8-bound (~5e-4 predicted). s32 accs exact over full K.
//     Q-GEMM stays fp16 f32-acc (R6 structure). Row compaction kept.
// ============================================================================

#define EPS 1e-6f
constexpr int NROWS = 65536;
constexpr int HID   = 1024;
constexpr int KC    = 64;                // k-chunk (elements)
constexpr int NCH   = HID / KC;          // 16
constexpr int STG   = 3;

// fp16 Q-GEMM tiling (unchanged from R6, fp16 types)
constexpr int TPAD   = 72;               // fp16 row stride elems (144B)
constexpr int TILE_B = 128 * TPAD * 2;   // 18432 B
constexpr int SMEM_Q = 512 + STG * 2 * TILE_B;   // 111104

// int8 KV tiling: CTA tile 128(m) x 64(n), chunk K=64, row stride 80B
constexpr int RS      = 80;
constexpr int AT_B    = 128 * RS;        // 10240
constexpr int BT_B    = 64 * RS;         // 5120
constexpr int STAGE_B = 2 * AT_B + 2 * BT_B;   // 30720
constexpr int SMEM_KV = 1024 + STG * STAGE_B;  // 93184

// ---------------- scratch (device globals; no allocation allowed) -----------
__device__ __align__(16) __half g_h  [67108864];   // rmsnorm(x) fp16 (compacted)
__device__ __align__(16) __half g_xq [67108864];   // q projection fp16
__device__ __align__(16) __half g_wq [1048576];
__device__ __align__(16) signed char g_y8h[67108864];
__device__ __align__(16) signed char g_y8l[67108864];
__device__ __align__(16) signed char g_wk8[1048576];
__device__ __align__(16) signed char g_wv8[1048576];
__device__ __align__(16) float g_ysc [NROWS];
__device__ __align__(16) float g_wksc[HID];
__device__ __align__(16) float g_wvsc[HID];
__device__ __align__(16) int g_list[NROWS];
__device__ __align__(16) int g_pos [NROWS];
__device__ __align__(16) int g_rep2[NROWS];
__device__ __align__(16) unsigned char g_flag[NROWS];
__device__ int g_cnt[2];

// ---------------- helpers ----------------------------------------------------
__device__ __forceinline__ uint32_t smem_u32(const void* p) {
    uint32_t a;
    asm("{ .reg .u64 t; cvta.to.shared.u64 t, %1; cvt.u32.u64 %0, t; }" : "=r"(a) : "l"(p));
    return a;
}
__device__ __forceinline__ void cp_async16(uint32_t dst, const void* src) {
    asm volatile("cp.async.cg.shared.global [%0], [%1], 16;" :: "r"(dst), "l"(src) : "memory");
}
#define CP_COMMIT() asm volatile("cp.async.commit_group;" ::: "memory")
#define CP_WAIT(n)  asm volatile("cp.async.wait_group %0;" :: "n"(n) : "memory")

__device__ __forceinline__ void ldm_x4(uint32_t* r, uint32_t addr) {
    asm volatile("ldmatrix.sync.aligned.m8n8.x4.shared.b16 {%0,%1,%2,%3}, [%4];"
                 : "=r"(r[0]), "=r"(r[1]), "=r"(r[2]), "=r"(r[3]) : "r"(addr));
}
__device__ __forceinline__ void mma_bf(float* d, const uint32_t* a, const uint32_t* b) {
    asm volatile(
        "mma.sync.aligned.m16n8k16.row.col.f32.f16.f16.f32 "
        "{%0,%1,%2,%3}, {%4,%5,%6,%7}, {%8,%9}, {%0,%1,%2,%3};"
        : "+f"(d[0]), "+f"(d[1]), "+f"(d[2]), "+f"(d[3])
        : "r"(a[0]), "r"(a[1]), "r"(a[2]), "r"(a[3]), "r"(b[0]), "r"(b[1]));
}
__device__ __forceinline__ void imma(int* d, const uint32_t* a, uint32_t b0, uint32_t b1) {
    asm volatile(
        "mma.sync.aligned.m16n8k32.row.col.s32.s8.s8.s32 "
        "{%0,%1,%2,%3}, {%4,%5,%6,%7}, {%8,%9}, {%0,%1,%2,%3};"
        : "+r"(d[0]), "+r"(d[1]), "+r"(d[2]), "+r"(d[3])
        : "r"(a[0]), "r"(a[1]), "r"(a[2]), "r"(a[3]), "r"(b0), "r"(b1));
}

// fp16 tile loader (Q GEMM): 128 rows x 64 cols, stride 144B, 256 thr
__device__ __forceinline__ void load_tile_h(uint32_t sbase, const __half* __restrict__ g,
                                            int row0, int col0) {
    const int tid = threadIdx.x;
#pragma unroll
    for (int k = 0; k < 4; k++) {
        int u = tid + k * 256;
        int r = u >> 3, c = u & 7;
        cp_async16(sbase + r * (TPAD * 2) + c * 16,
                   g + (size_t)(row0 + r) * HID + col0 + c * 8);
    }
}
// int8 tile loaders: 64B of k per row, stride 80B
__device__ __forceinline__ void load_a8(uint32_t sbase, const signed char* __restrict__ g,
                                        int row0, int col0) {
    const int tid = threadIdx.x;
#pragma unroll
    for (int k = 0; k < 2; k++) {
        int u = tid + k * 256;              // 512 units
        int r = u >> 2, c = u & 3;
        cp_async16(sbase + r * RS + c * 16,
                   g + (size_t)(row0 + r) * HID + col0 + c * 16);
    }
}
__device__ __forceinline__ void load_b8(uint32_t sbase, const signed char* __restrict__ g,
                                        int row0, int col0) {
    const int tid = threadIdx.x;            // 256 units, 1 per thread
    int r = tid >> 2, c = tid & 3;
    cp_async16(sbase + r * RS + c * 16,
               g + (size_t)(row0 + r) * HID + col0 + c * 16);
}

// ---------------- compaction -------------------------------------------------
__global__ void __launch_bounds__(1024) k_zero() {
    reinterpret_cast<int*>(g_flag)[blockIdx.x * 1024 + threadIdx.x] = 0;
}
__global__ void __launch_bounds__(1024) k_mark(const int* __restrict__ rep) {
    g_flag[rep[blockIdx.x * 1024 + threadIdx.x]] = 1;
}
__global__ void __launch_bounds__(1024) k_scan() {
    __shared__ int wsum[32];
    int t = threadIdx.x, lane = t & 31, w = t >> 5;
    int base = t * 64;
    int s = 0;
#pragma unroll 8
    for (int j = 0; j < 64; j++) s += g_flag[base + j];
    int v = s;
#pragma unroll
    for (int o = 1; o < 32; o <<= 1) {
        int u = __shfl_up_sync(0xffffffffu, v, o);
        if (lane >= o) v += u;
    }
    if (lane == 31) wsum[w] = v;
    __syncthreads();
    if (w == 0) {
        int x2 = wsum[lane];
#pragma unroll
        for (int o = 1; o < 32; o <<= 1) {
            int u = __shfl_up_sync(0xffffffffu, x2, o);
            if (lane >= o) x2 += u;
        }
        wsum[lane] = x2;
    }
    __syncthreads();
    int excl = v - s + (w ? wsum[w - 1] : 0);
    int idx = excl;
    for (int j = 0; j < 64; j++) {
        int r = base + j;
        if (g_flag[r]) { g_list[idx] = r; g_pos[r] = idx; idx++; }
    }
    if (t == 1023) {
        int tot = excl + s;
        g_cnt[0] = tot;
        g_cnt[1] = (tot + 127) & ~127;
    }
}
__global__ void __launch_bounds__(1024) k_remap(const int* __restrict__ rep) {
    int i = blockIdx.x * 1024 + threadIdx.x;
    g_rep2[i] = g_pos[rep[i]];
}

// ---------------- prep -------------------------------------------------------
__global__ void __launch_bounds__(256) k_rmsnorm(const float* __restrict__ x,
                                                 const float* __restrict__ w) {
    int ci   = (blockIdx.x * 256 + threadIdx.x) >> 5;
    int lane = threadIdx.x & 31;
    int cnt = g_cnt[0], cpad = g_cnt[1];
    if (ci >= cpad) return;
    uint2* hp = reinterpret_cast<uint2*>(g_h + (size_t)ci * HID);
    if (ci >= cnt) {
        uint2 z = make_uint2(0u, 0u);
#pragma unroll
        for (int i = 0; i < 8; i++) hp[lane + i * 32] = z;
        return;
    }
    int row = g_list[ci];
    const float4* xp = reinterpret_cast<const float4*>(x + (size_t)row * HID);
    float4 v[8];
    float ss = 0.f;
#pragma unroll
    for (int i = 0; i < 8; i++) {
        v[i] = xp[lane + i * 32];
        ss += v[i].x * v[i].x + v[i].y * v[i].y + v[i].z * v[i].z + v[i].w * v[i].w;
    }
#pragma unroll
    for (int o = 16; o > 0; o >>= 1) ss += __shfl_xor_sync(0xffffffffu, ss, o);
    float rs = rsqrtf(ss * (1.0f / HID) + EPS);
    const float4* wp = reinterpret_cast<const float4*>(w);
#pragma unroll
    for (int i = 0; i < 8; i++) {
        float4 wv = wp[lane + i * 32];
        __half2 p0 = __floats2half2_rn(v[i].x * rs * wv.x, v[i].y * rs * wv.y);
        __half2 p1 = __floats2half2_rn(v[i].z * rs * wv.z, v[i].w * rs * wv.w);
        uint2 s;
        s.x = *reinterpret_cast<uint32_t*>(&p0);
        s.y = *reinterpret_cast<uint32_t*>(&p1);
        hp[lane + i * 32] = s;
    }
}

// quantize y rows: s = rowmax/127; hi = rint(y/s); lo = rint((y/s - hi)*254)
__global__ void __launch_bounds__(256) k_quant_y(const float* __restrict__ y) {
    int row  = (blockIdx.x * 256 + threadIdx.x) >> 5;
    int lane = threadIdx.x & 31;
    const float4* yp = reinterpret_cast<const float4*>(y + (size_t)row * HID);
    float4 v[8];
    float mx = 0.f;
#pragma unroll
    for (int i = 0; i < 8; i++) {
        v[i] = yp[lane + i * 32];
        mx = fmaxf(mx, fmaxf(fmaxf(fabsf(v[i].x), fabsf(v[i].y)),
                             fmaxf(fabsf(v[i].z), fabsf(v[i].w))));
    }
#pragma unroll
    for (int o = 16; o > 0; o >>= 1) mx = fmaxf(mx, __shfl_xor_sync(0xffffffffu, mx, o));
    float s = fmaxf(mx, 1e-20f) * (1.0f / 127.0f);
    float inv = 1.0f / s;
    if (lane == 0) g_ysc[row] = s;
    uint32_t* hp = reinterpret_cast<uint32_t*>(g_y8h + (size_t)row * HID);
    uint32_t* lp = reinterpret_cast<uint32_t*>(g_y8l + (size_t)row * HID);
#pragma unroll
    for (int i = 0; i < 8; i++) {
        float f[4] = {v[i].x * inv, v[i].y * inv, v[i].z * inv, v[i].w * inv};
        uint32_t ph = 0, pl = 0;
#pragma unroll
        for (int j = 0; j < 4; j++) {
            int hi = (int)rintf(f[j]);
            int lo = (int)rintf((f[j] - (float)hi) * 254.0f);
            ph |= ((uint32_t)hi & 0xffu) << (8 * j);
            pl |= ((uint32_t)lo & 0xffu) << (8 * j);
        }
        hp[lane + i * 32] = ph;
        lp[lane + i * 32] = pl;
    }
}

// quantize weight rows (k and v): per-output-row scale
__global__ void __launch_bounds__(256) k_quant_w(const float* __restrict__ kw,
                                                 const float* __restrict__ vw) {
    int rg   = (blockIdx.x * 256 + threadIdx.x) >> 5;   // 0..2047
    int lane = threadIdx.x & 31;
    int which = rg >> 10, row = rg & 1023;
    const float* src = which ? vw : kw;
    signed char* dst = which ? g_wv8 : g_wk8;
    float* scl = which ? g_wvsc : g_wksc;
    const float4* wp = reinterpret_cast<const float4*>(src + (size_t)row * HID);
    float4 v[8];
    float mx = 0.f;
#pragma unroll
    for (int i = 0; i < 8; i++) {
        v[i] = wp[lane + i * 32];
        mx = fmaxf(mx, fmaxf(fmaxf(fabsf(v[i].x), fabsf(v[i].y)),
                             fmaxf(fabsf(v[i].z), fabsf(v[i].w))));
    }
#pragma unroll
    for (int o = 16; o > 0; o >>= 1) mx = fmaxf(mx, __shfl_xor_sync(0xffffffffu, mx, o));
    float s = fmaxf(mx, 1e-20f) * (1.0f / 127.0f);
    float inv = 1.0f / s;
    if (lane == 0) scl[row] = s;
    uint32_t* dp = reinterpret_cast<uint32_t*>(dst + (size_t)row * HID);
#pragma unroll
    for (int i = 0; i < 8; i++) {
        float f[4] = {v[i].x * inv, v[i].y * inv, v[i].z * inv, v[i].w * inv};
        uint32_t p = 0;
#pragma unroll
        for (int j = 0; j < 4; j++) {
            int q = (int)rintf(f[j]);
            p |= ((uint32_t)q & 0xffu) << (8 * j);
        }
        dp[lane + i * 32] = p;
    }
}

__global__ void __launch_bounds__(256) k_convert_wq(const float* __restrict__ qw) {
    int i = blockIdx.x * 256 + threadIdx.x;
    float4 v = reinterpret_cast<const float4*>(qw)[i];
    __half2 p0 = __floats2half2_rn(v.x, v.y);
    __half2 p1 = __floats2half2_rn(v.z, v.w);
    uint2 s;
    s.x = *reinterpret_cast<uint32_t*>(&p0);
    s.y = *reinterpret_cast<uint32_t*>(&p1);
    reinterpret_cast<uint2*>(g_wq)[i] = s;
}

// ---------------- GEMM-Q: fp16, f32 acc, 256 thr, 3-stage (R6 structure) -----
__global__ void __launch_bounds__(256, 1) k_gemm_q(const float* __restrict__ qb) {
    const int n0 = blockIdx.x * 128, m0 = blockIdx.y * 128;
    if (m0 >= g_cnt[1]) return;
    extern __shared__ char smem[];
    const int tid = threadIdx.x, w = tid >> 5, l = tid & 31;
    const int wr = w >> 1, wc = w & 1;
    float* qb_s = reinterpret_cast<float*>(smem);
    uint32_t sb = smem_u32(smem) + 512;

    if (tid < 128) qb_s[tid] = qb[n0 + tid];
    load_tile_h(sb,                       g_h,  m0, 0);
    load_tile_h(sb + TILE_B,              g_wq, n0, 0);
    CP_COMMIT();
    load_tile_h(sb + 2 * TILE_B,          g_h,  m0, KC);
    load_tile_h(sb + 2 * TILE_B + TILE_B, g_wq, n0, KC);
    CP_COMMIT();

    float acc[2][8][4];
#pragma unroll
    for (int mt = 0; mt < 2; mt++)
#pragma unroll
        for (int nt = 0; nt < 8; nt++)
#pragma unroll
            for (int i = 0; i < 4; i++) acc[mt][nt][i] = 0.f;

    const int a_row = wr * 32 + (l & 7) + ((l >> 3) & 1) * 8;
    const int a_kb  = (l >> 4) * 16;
    const int b_row = wc * 64 + ((l >> 4) & 1) * 8 + (l & 7);
    const int b_kb  = ((l >> 3) & 1) * 16;

    for (int ci = 0; ci < NCH; ci++) {
        CP_WAIT(1);
        __syncthreads();
        if (ci + 2 < NCH) {
            uint32_t tb = sb + (uint32_t)((ci + 2) % STG) * (2 * TILE_B);
            load_tile_h(tb,          g_h,  m0, (ci + 2) * KC);
            load_tile_h(tb + TILE_B, g_wq, n0, (ci + 2) * KC);
        }
        CP_COMMIT();

        uint32_t sA = sb + (uint32_t)(ci % STG) * (2 * TILE_B);
        uint32_t sB = sA + TILE_B;
#pragma unroll
        for (int ks = 0; ks < 4; ks++) {
            uint32_t af[2][4], bf[4][4];
#pragma unroll
            for (int mt = 0; mt < 2; mt++)
                ldm_x4(af[mt], sA + (a_row + mt * 16) * (TPAD * 2) + ks * 32 + a_kb);
#pragma unroll
            for (int np = 0; np < 4; np++)
                ldm_x4(bf[np], sB + (b_row + np * 16) * (TPAD * 2) + ks * 32 + b_kb);
#pragma unroll
            for (int mt = 0; mt < 2; mt++)
#pragma unroll
                for (int np = 0; np < 4; np++) {
                    mma_bf(acc[mt][2 * np],     af[mt], bf[np]);
                    mma_bf(acc[mt][2 * np + 1], af[mt], bf[np] + 2);
                }
        }
    }

#pragma unroll
    for (int mt = 0; mt < 2; mt++)
#pragma unroll
        for (int nt = 0; nt < 8; nt++) {
            int col = wc * 64 + nt * 8 + 2 * (l & 3);
            float b0 = qb_s[col], b1 = qb_s[col + 1];
            int r0 = m0 + wr * 32 + mt * 16 + (l >> 2);
            __half2 p0 = __floats2half2_rn(acc[mt][nt][0] + b0, acc[mt][nt][1] + b1);
            __half2 p1 = __floats2half2_rn(acc[mt][nt][2] + b0, acc[mt][nt][3] + b1);
            *reinterpret_cast<__half2*>(g_xq + (size_t)r0 * HID + n0 + col) = p0;
            *reinterpret_cast<__half2*>(g_xq + (size_t)(r0 + 8) * HID + n0 + col) = p1;
        }
}

// -------- fused int8 GEMM-KV + attention epilogue: CTA 128x64, 8 warps -------
__global__ void __launch_bounds__(256, 1) k_gemm_kv(const float* __restrict__ x,
                                                    const float* __restrict__ kb,
                                                    const float* __restrict__ vb,
                                                    float* __restrict__ out) {
    extern __shared__ char smem[];
    const int tid = threadIdx.x, w = tid >> 5, l = tid & 31;
    const int n0 = blockIdx.x * 64, m0 = blockIdx.y * 128;
    float* kb_s  = reinterpret_cast<float*>(smem);        // 64
    float* vb_s  = kb_s + 64;
    float* swk_s = kb_s + 128;
    float* swv_s = kb_s + 192;
    uint32_t sb = smem_u32(smem) + 1024;

    if (tid < 64) {
        kb_s[tid]  = kb[n0 + tid];
        vb_s[tid]  = vb[n0 + tid];
        swk_s[tid] = g_wksc[n0 + tid];
        swv_s[tid] = g_wvsc[n0 + tid];
    }
    // preamble stages 0,1
#pragma unroll
    for (int st = 0; st < 2; st++) {
        uint32_t tb = sb + st * STAGE_B;
        load_a8(tb,               g_y8h, m0, st * KC);
        load_a8(tb + AT_B,        g_y8l, m0, st * KC);
        load_b8(tb + 2 * AT_B,        g_wk8, n0, st * KC);
        load_b8(tb + 2 * AT_B + BT_B, g_wv8, n0, st * KC);
        CP_COMMIT();
    }

    int aKh[8][4], aKl[8][4], aVh[8][4], aVl[8][4];
#pragma unroll
    for (int nt = 0; nt < 8; nt++)
#pragma unroll
        for (int i = 0; i < 4; i++) { aKh[nt][i] = 0; aKl[nt][i] = 0; aVh[nt][i] = 0; aVl[nt][i] = 0; }

    const int a_off = (w * 16 + (l & 7) + ((l >> 3) & 1) * 8) * RS + ((l >> 4) & 1) * 16;
    const int b_off = ((l & 7) + ((l >> 3) & 1) * 8) * RS + ((l >> 4) & 1) * 16;

    for (int ci = 0; ci < NCH; ci++) {
        CP_WAIT(1);
        __syncthreads();
        if (ci + 2 < NCH) {
            uint32_t tb = sb + (uint32_t)((ci + 2) % STG) * STAGE_B;
            load_a8(tb,               g_y8h, m0, (ci + 2) * KC);
            load_a8(tb + AT_B,        g_y8l, m0, (ci + 2) * KC);
            load_b8(tb + 2 * AT_B,        g_wk8, n0, (ci + 2) * KC);
            load_b8(tb + 2 * AT_B + BT_B, g_wv8, n0, (ci + 2) * KC);
        }
        CP_COMMIT();

        uint32_t sAh = sb + (uint32_t)(ci % STG) * STAGE_B;
        uint32_t sAl = sAh + AT_B;
        uint32_t sBk = sAh + 2 * AT_B;
        uint32_t sBv = sBk + BT_B;
#pragma unroll
        for (int ks = 0; ks < 2; ks++) {
            uint32_t ah[4], al[4], bk[4][4], bv[4][4];
            ldm_x4(ah, sAh + a_off + ks * 32);
            ldm_x4(al, sAl + a_off + ks * 32);
#pragma unroll
            for (int nb = 0; nb < 4; nb++) {
                uint32_t off = b_off + nb * 16 * RS + ks * 32;
                ldm_x4(bk[nb], sBk + off);
                ldm_x4(bv[nb], sBv + off);
            }
#pragma unroll
            for (int nb = 0; nb < 4; nb++) {
                imma(aKh[2 * nb],     ah, bk[nb][0], bk[nb][2]);
                imma(aKh[2 * nb + 1], ah, bk[nb][1], bk[nb][3]);
                imma(aKl[2 * nb],     al, bk[nb][0], bk[nb][2]);
                imma(aKl[2 * nb + 1], al, bk[nb][1], bk[nb][3]);
                imma(aVh[2 * nb],     ah, bv[nb][0], bv[nb][2]);
                imma(aVh[2 * nb + 1], ah, bv[nb][1], bv[nb][3]);
                imma(aVl[2 * nb],     al, bv[nb][0], bv[nb][2]);
                imma(aVl[2 * nb + 1], al, bv[nb][1], bv[nb][3]);
            }
        }
    }

    // ---- epilogue: warp owns rows w*16..+15, the CTA's 64 cols = one head
    const float ILO = 1.0f / 254.0f;
    int r0l = w * 16 + (l >> 2);
    int grow[2] = {m0 + r0l, m0 + r0l + 8};
    float sA[2] = {g_ysc[grow[0]], g_ysc[grow[1]]};
    int qrow[2] = {g_rep2[grow[0]], g_rep2[grow[1]]};

    float dp[2] = {0, 0}, qn2[2] = {0, 0}, kn2[2] = {0, 0};
#pragma unroll
    for (int nt = 0; nt < 8; nt++) {
        int col = nt * 8 + 2 * (l & 3);
        float wk0 = swk_s[col], wk1 = swk_s[col + 1];
        float kb0 = kb_s[col],  kb1 = kb_s[col + 1];
#pragma unroll
        for (int p = 0; p < 2; p++) {
            float k0 = sA[p] * wk0 * ((float)aKh[nt][2 * p]     + (float)aKl[nt][2 * p]     * ILO) + kb0;
            float k1 = sA[p] * wk1 * ((float)aKh[nt][2 * p + 1] + (float)aKl[nt][2 * p + 1] * ILO) + kb1;
            float2 qf = __half22float2(*reinterpret_cast<const __half2*>(
                g_xq + (size_t)qrow[p] * HID + n0 + col));
            dp[p]  += qf.x * k0 + qf.y * k1;
            qn2[p] += qf.x * qf.x + qf.y * qf.y;
            kn2[p] += k0 * k0 + k1 * k1;
        }
    }
#pragma unroll
    for (int o = 1; o <= 2; o <<= 1)
#pragma unroll
        for (int p = 0; p < 2; p++) {
            dp[p]  += __shfl_xor_sync(0xffffffffu, dp[p],  o);
            qn2[p] += __shfl_xor_sync(0xffffffffu, qn2[p], o);
            kn2[p] += __shfl_xor_sync(0xffffffffu, kn2[p], o);
        }
    float att[2];
#pragma unroll
    for (int p = 0; p < 2; p++)
        att[p] = dp[p] / (fmaxf(sqrtf(qn2[p]), EPS) * fmaxf(sqrtf(kn2[p]), EPS));

#pragma unroll
    for (int nt = 0; nt < 8; nt++) {
        int col = nt * 8 + 2 * (l & 3);
        float wv0 = swv_s[col], wv1 = swv_s[col + 1];
        float vb0 = vb_s[col],  vb1 = vb_s[col + 1];
#pragma unroll
        for (int p = 0; p < 2; p++) {
            float v0 = sA[p] * wv0 * ((float)aVh[nt][2 * p]     + (float)aVl[nt][2 * p]     * ILO) + vb0;
            float v1 = sA[p] * wv1 * ((float)aVh[nt][2 * p + 1] + (float)aVl[nt][2 * p + 1] * ILO) + vb1;
            const float2 xv = *reinterpret_cast<const float2*>(
                x + (size_t)grow[p] * HID + n0 + col);
            float2 o;
            o.x = xv.x + v0 * att[p];
            o.y = xv.y + v1 * att[p];
            *reinterpret_cast<float2*>(out + (size_t)grow[p] * HID + n0 + col) = o;
        }
    }
}

// ---------------- launch -----------------------------------------------------
extern "C" void kernel_launch(void* const* d_in, const int* in_sizes, int n_in,
                              void* d_out, int out_size) {
    const float* x    = (const float*)d_in[0];
    const float* y    = (const float*)d_in[1];
    const int*   rep  = (const int*)d_in[2];
    const float* ln_w = (const float*)d_in[3];
    const float* q_w  = (const float*)d_in[4];
    const float* q_b  = (const float*)d_in[5];
    const float* k_w  = (const float*)d_in[6];
    const float* k_b  = (const float*)d_in[7];
    const float* v_w  = (const float*)d_in[8];
    const float* v_b  = (const float*)d_in[9];
    float* out = (float*)d_out;

    cudaFuncSetAttribute(k_gemm_q,  cudaFuncAttributeMaxDynamicSharedMemorySize, SMEM_Q);
    cudaFuncSetAttribute(k_gemm_kv, cudaFuncAttributeMaxDynamicSharedMemorySize, SMEM_KV);

    k_zero<<<16, 1024>>>();
    k_mark<<<64, 1024>>>(rep);
    k_scan<<<1, 1024>>>();
    k_remap<<<64, 1024>>>(rep);

    k_rmsnorm<<<NROWS / 8, 256>>>(x, ln_w);
    k_quant_y<<<NROWS / 8, 256>>>(y);
    k_quant_w<<<2048 / 8, 256>>>(k_w, v_w);
    k_convert_wq<<<HID * HID / 4 / 256, 256>>>(q_w);

    dim3 gq(HID / 128, NROWS / 128);     // (8, 512), inactive row-tiles exit
    k_gemm_q<<<gq, 256, SMEM_Q>>>(q_b);
    dim3 gkv(HID / 64, NROWS / 128);     // (16, 512)
    k_gemm_kv<<<gkv, 256, SMEM_KV>>>(x, k_b, v_b, out);
}

// round 9
// speedup vs baseline: 1.9920x; 1.9920x over previous
#include <cuda_runtime.h>
#include <cuda_fp16.h>
#include <cstdint>

// ============================================================================
// ResAttentionBlock (ptxas target sm_103 rejects tcgen05 -> legacy mma.sync).
// R9: fp16 inputs + f32-acc HMMA (rt=8/SMSP, same as bf16, 4x less quant err);
//     2-stage cp.async ring + __launch_bounds__(256,2) so 2 CTAs/SM overlap
//     epilogue memory phases with the other CTA's HMMA mainloop.
//     Row compaction kept (Q GEMM only over ~63% gathered rows).
// ============================================================================

#define EPS 1e-6f
constexpr int NROWS = 65536;
constexpr int HID   = 1024;
constexpr int KC    = 64;              // k-chunk (elements)
constexpr int NCH   = HID / KC;        // 16
constexpr int TPAD  = 72;              // padded row stride in fp16 elems (144B)
constexpr int TILE_B = 128 * TPAD * 2; // one 128x64 fp16 tile = 18432 B
constexpr int STG   = 2;               // pipeline stages (2 => 2 CTAs/SM)

constexpr int SMEM_Q  = 512  + STG * 2 * TILE_B;   // 74240
constexpr int SMEM_KV = 1024 + STG * 3 * TILE_B;   // 111616

// ---------------- scratch (device globals; no allocation allowed) -----------
__device__ __align__(16) __half g_h [67108864];
__device__ __align__(16) __half g_yb[67108864];
__device__ __align__(16) __half g_xq[67108864];
__device__ __align__(16) __half g_wq[1048576];
__device__ __align__(16) __half g_wk[1048576];
__device__ __align__(16) __half g_wv[1048576];
__device__ __align__(16) int g_list[NROWS];     // compacted -> original row
__device__ __align__(16) int g_pos [NROWS];     // original row -> compacted
__device__ __align__(16) int g_rep2[NROWS];     // pos[rep[i]]
__device__ __align__(16) unsigned char g_flag[NROWS];
__device__ int g_cnt[2];                         // [0]=count, [1]=padded

// ---------------- helpers ----------------------------------------------------
__device__ __forceinline__ uint32_t smem_u32(const void* p) {
    uint32_t a;
    asm("{ .reg .u64 t; cvta.to.shared.u64 t, %1; cvt.u32.u64 %0, t; }" : "=r"(a) : "l"(p));
    return a;
}
__device__ __forceinline__ void cp_async16(uint32_t dst, const void* src) {
    asm volatile("cp.async.cg.shared.global [%0], [%1], 16;" :: "r"(dst), "l"(src) : "memory");
}
#define CP_COMMIT() asm volatile("cp.async.commit_group;" ::: "memory")
#define CP_WAIT(n)  asm volatile("cp.async.wait_group %0;" :: "n"(n) : "memory")

__device__ __forceinline__ void ldm_x4(uint32_t* r, uint32_t addr) {
    asm volatile("ldmatrix.sync.aligned.m8n8.x4.shared.b16 {%0,%1,%2,%3}, [%4];"
                 : "=r"(r[0]), "=r"(r[1]), "=r"(r[2]), "=r"(r[3]) : "r"(addr));
}
__device__ __forceinline__ void mma_h32(float* d, const uint32_t* a, const uint32_t* b) {
    asm volatile(
        "mma.sync.aligned.m16n8k16.row.col.f32.f16.f16.f32 "
        "{%0,%1,%2,%3}, {%4,%5,%6,%7}, {%8,%9}, {%0,%1,%2,%3};"
        : "+f"(d[0]), "+f"(d[1]), "+f"(d[2]), "+f"(d[3])
        : "r"(a[0]), "r"(a[1]), "r"(a[2]), "r"(a[3]), "r"(b[0]), "r"(b[1]));
}

// Load one 128-row x 64-col fp16 tile into padded smem (stride 144B). 256 thr.
__device__ __forceinline__ void load_tile(uint32_t sbase, const __half* __restrict__ g,
                                          int row0, int col0) {
    const int tid = threadIdx.x;
#pragma unroll
    for (int k = 0; k < 4; k++) {
        int u = tid + k * 256;              // 1024 16B units (8 per row)
        int r = u >> 3, c = u & 7;
        cp_async16(sbase + r * (TPAD * 2) + c * 16,
                   g + (size_t)(row0 + r) * HID + col0 + c * 8);
    }
}

// ---------------- compaction kernels -----------------------------------------
__global__ void __launch_bounds__(1024) k_zero() {
    reinterpret_cast<int*>(g_flag)[blockIdx.x * 1024 + threadIdx.x] = 0;
}
__global__ void __launch_bounds__(1024) k_mark(const int* __restrict__ rep) {
    g_flag[rep[blockIdx.x * 1024 + threadIdx.x]] = 1;   // idempotent race
}
__global__ void __launch_bounds__(1024) k_scan() {      // single CTA
    __shared__ int wsum[32];
    int t = threadIdx.x, lane = t & 31, w = t >> 5;
    int base = t * 64;
    int s = 0;
#pragma unroll 8
    for (int j = 0; j < 64; j++) s += g_flag[base + j];
    int v = s;
#pragma unroll
    for (int o = 1; o < 32; o <<= 1) {
        int u = __shfl_up_sync(0xffffffffu, v, o);
        if (lane >= o) v += u;
    }
    if (lane == 31) wsum[w] = v;
    __syncthreads();
    if (w == 0) {
        int x2 = wsum[lane];
#pragma unroll
        for (int o = 1; o < 32; o <<= 1) {
            int u = __shfl_up_sync(0xffffffffu, x2, o);
            if (lane >= o) x2 += u;
        }
        wsum[lane] = x2;
    }
    __syncthreads();
    int excl = v - s + (w ? wsum[w - 1] : 0);
    int idx = excl;
    for (int j = 0; j < 64; j++) {
        int r = base + j;
        if (g_flag[r]) { g_list[idx] = r; g_pos[r] = idx; idx++; }
    }
    if (t == 1023) {
        int tot = excl + s;
        g_cnt[0] = tot;
        g_cnt[1] = (tot + 127) & ~127;
    }
}
__global__ void __launch_bounds__(1024) k_remap(const int* __restrict__ rep) {
    int i = blockIdx.x * 1024 + threadIdx.x;
    g_rep2[i] = g_pos[rep[i]];
}

// ---------------- prep kernels -----------------------------------------------
__global__ void __launch_bounds__(256) k_rmsnorm(const float* __restrict__ x,
                                                 const float* __restrict__ w) {
    int ci   = (blockIdx.x * 256 + threadIdx.x) >> 5;
    int lane = threadIdx.x & 31;
    int cnt = g_cnt[0], cpad = g_cnt[1];
    if (ci >= cpad) return;
    uint2* hp = reinterpret_cast<uint2*>(g_h + (size_t)ci * HID);
    if (ci >= cnt) {
        uint2 z = make_uint2(0u, 0u);
#pragma unroll
        for (int i = 0; i < 8; i++) hp[lane + i * 32] = z;
        return;
    }
    int row = g_list[ci];
    const float4* xp = reinterpret_cast<const float4*>(x + (size_t)row * HID);
    float4 v[8];
    float ss = 0.f;
#pragma unroll
    for (int i = 0; i < 8; i++) {
        v[i] = xp[lane + i * 32];
        ss += v[i].x * v[i].x + v[i].y * v[i].y + v[i].z * v[i].z + v[i].w * v[i].w;
    }
#pragma unroll
    for (int o = 16; o > 0; o >>= 1) ss += __shfl_xor_sync(0xffffffffu, ss, o);
    float rs = rsqrtf(ss * (1.0f / HID) + EPS);
    const float4* wp = reinterpret_cast<const float4*>(w);
#pragma unroll
    for (int i = 0; i < 8; i++) {
        float4 wv = wp[lane + i * 32];
        __half2 p0 = __floats2half2_rn(v[i].x * rs * wv.x, v[i].y * rs * wv.y);
        __half2 p1 = __floats2half2_rn(v[i].z * rs * wv.z, v[i].w * rs * wv.w);
        uint2 s;
        s.x = *reinterpret_cast<uint32_t*>(&p0);
        s.y = *reinterpret_cast<uint32_t*>(&p1);
        hp[lane + i * 32] = s;
    }
}

__global__ void __launch_bounds__(256) k_convert_y(const float* __restrict__ src) {
    int i = blockIdx.x * 256 + threadIdx.x;
    float4 v = reinterpret_cast<const float4*>(src)[i];
    __half2 p0 = __floats2half2_rn(v.x, v.y);
    __half2 p1 = __floats2half2_rn(v.z, v.w);
    uint2 s;
    s.x = *reinterpret_cast<uint32_t*>(&p0);
    s.y = *reinterpret_cast<uint32_t*>(&p1);
    reinterpret_cast<uint2*>(g_yb)[i] = s;
}

__global__ void __launch_bounds__(256) k_convert_w(const float* __restrict__ qw,
                                                   const float* __restrict__ kw,
                                                   const float* __restrict__ vw) {
    int which = blockIdx.x >> 10;
    int i = (blockIdx.x & 1023) * 256 + threadIdx.x;
    const float* src = (which == 0) ? qw : (which == 1) ? kw : vw;
    __half* dst = (which == 0) ? g_wq : (which == 1) ? g_wk : g_wv;
    float4 v = reinterpret_cast<const float4*>(src)[i];
    __half2 p0 = __floats2half2_rn(v.x, v.y);
    __half2 p1 = __floats2half2_rn(v.z, v.w);
    uint2 s;
    s.x = *reinterpret_cast<uint32_t*>(&p0);
    s.y = *reinterpret_cast<uint32_t*>(&p1);
    reinterpret_cast<uint2*>(dst)[i] = s;
}

// ---------------- GEMM-Q: 256 thr, warp tile 32x64, 2-stage, 2 CTA/SM --------
__global__ void __launch_bounds__(256, 2) k_gemm_q(const float* __restrict__ qb) {
    const int n0 = blockIdx.x * 128, m0 = blockIdx.y * 128;
    if (m0 >= g_cnt[1]) return;            // beyond compacted rows
    extern __shared__ char smem[];
    const int tid = threadIdx.x, w = tid >> 5, l = tid & 31;
    const int wr = w >> 1, wc = w & 1;     // warp grid 4x2, warp tile 32x64
    float* qb_s = reinterpret_cast<float*>(smem);
    uint32_t sb = smem_u32(smem) + 512;

    if (tid < 128) qb_s[tid] = qb[n0 + tid];
    load_tile(sb,          g_h,  m0, 0);
    load_tile(sb + TILE_B, g_wq, n0, 0);
    CP_COMMIT();

    float acc[2][8][4];
#pragma unroll
    for (int mt = 0; mt < 2; mt++)
#pragma unroll
        for (int nt = 0; nt < 8; nt++)
#pragma unroll
            for (int i = 0; i < 4; i++) acc[mt][nt][i] = 0.f;

    const int a_row = wr * 32 + (l & 7) + ((l >> 3) & 1) * 8;
    const int a_kb  = (l >> 4) * 16;
    const int b_row = wc * 64 + ((l >> 4) & 1) * 8 + (l & 7);
    const int b_kb  = ((l >> 3) & 1) * 16;

    for (int ci = 0; ci < NCH; ci++) {
        CP_WAIT(0);                 // chunk ci resident
        __syncthreads();            // all warps done reading the other buffer
        if (ci + 1 < NCH) {
            uint32_t tb = sb + (uint32_t)((ci + 1) & 1) * (2 * TILE_B);
            load_tile(tb,          g_h,  m0, (ci + 1) * KC);
            load_tile(tb + TILE_B, g_wq, n0, (ci + 1) * KC);
            CP_COMMIT();
        }
        uint32_t sA = sb + (uint32_t)(ci & 1) * (2 * TILE_B);
        uint32_t sB = sA + TILE_B;
#pragma unroll
        for (int ks = 0; ks < 4; ks++) {
            uint32_t af[2][4], bf[4][4];
#pragma unroll
            for (int mt = 0; mt < 2; mt++)
                ldm_x4(af[mt], sA + (a_row + mt * 16) * (TPAD * 2) + ks * 32 + a_kb);
#pragma unroll
            for (int np = 0; np < 4; np++)
                ldm_x4(bf[np], sB + (b_row + np * 16) * (TPAD * 2) + ks * 32 + b_kb);
#pragma unroll
            for (int mt = 0; mt < 2; mt++)
#pragma unroll
                for (int np = 0; np < 4; np++) {
                    mma_h32(acc[mt][2 * np],     af[mt], bf[np]);
                    mma_h32(acc[mt][2 * np + 1], af[mt], bf[np] + 2);
                }
        }
    }

    // epilogue: +bias, fp16, store
#pragma unroll
    for (int mt = 0; mt < 2; mt++)
#pragma unroll
        for (int nt = 0; nt < 8; nt++) {
            int col = wc * 64 + nt * 8 + 2 * (l & 3);
            float b0 = qb_s[col], b1 = qb_s[col + 1];
            int r0 = m0 + wr * 32 + mt * 16 + (l >> 2);
            __half2 p0 = __floats2half2_rn(acc[mt][nt][0] + b0, acc[mt][nt][1] + b1);
            __half2 p1 = __floats2half2_rn(acc[mt][nt][2] + b0, acc[mt][nt][3] + b1);
            *reinterpret_cast<__half2*>(g_xq + (size_t)r0 * HID + n0 + col) = p0;
            *reinterpret_cast<__half2*>(g_xq + (size_t)(r0 + 8) * HID + n0 + col) = p1;
        }
}

// -------- fused GEMM-KV + attention epilogue: 2-stage, 2 CTA/SM --------------
__global__ void __launch_bounds__(256, 2) k_gemm_kv(const float* __restrict__ x,
                                                    const float* __restrict__ kb,
                                                    const float* __restrict__ vb,
                                                    float* __restrict__ out) {
    extern __shared__ char smem[];
    const int tid = threadIdx.x, w = tid >> 5, l = tid & 31;
    const int wr = w >> 1, wc = w & 1;
    const int n0 = blockIdx.x * 128, m0 = blockIdx.y * 128;
    float* kb_s = reinterpret_cast<float*>(smem);
    float* vb_s = kb_s + 128;
    uint32_t sb = smem_u32(smem) + 1024;

    if (tid < 128) { kb_s[tid] = kb[n0 + tid]; vb_s[tid] = vb[n0 + tid]; }
    load_tile(sb,              g_yb, m0, 0);
    load_tile(sb + TILE_B,     g_wk, n0, 0);
    load_tile(sb + 2 * TILE_B, g_wv, n0, 0);
    CP_COMMIT();

    float accK[2][8][4], accV[2][8][4];
#pragma unroll
    for (int mt = 0; mt < 2; mt++)
#pragma unroll
        for (int nt = 0; nt < 8; nt++)
#pragma unroll
            for (int i = 0; i < 4; i++) { accK[mt][nt][i] = 0.f; accV[mt][nt][i] = 0.f; }

    const int a_row = wr * 32 + (l & 7) + ((l >> 3) & 1) * 8;
    const int a_kb  = (l >> 4) * 16;
    const int b_row = wc * 64 + ((l >> 4) & 1) * 8 + (l & 7);
    const int b_kb  = ((l >> 3) & 1) * 16;

    for (int ci = 0; ci < NCH; ci++) {
        CP_WAIT(0);
        __syncthreads();
        if (ci + 1 < NCH) {
            uint32_t tb = sb + (uint32_t)((ci + 1) & 1) * (3 * TILE_B);
            load_tile(tb,              g_yb, m0, (ci + 1) * KC);
            load_tile(tb + TILE_B,     g_wk, n0, (ci + 1) * KC);
            load_tile(tb + 2 * TILE_B, g_wv, n0, (ci + 1) * KC);
            CP_COMMIT();
        }
        uint32_t sA  = sb + (uint32_t)(ci & 1) * (3 * TILE_B);
        uint32_t sBk = sA + TILE_B;
        uint32_t sBv = sA + 2 * TILE_B;
#pragma unroll
        for (int ks = 0; ks < 4; ks++) {
            uint32_t af[2][4], bk[4][4], bv[4][4];
#pragma unroll
            for (int mt = 0; mt < 2; mt++)
                ldm_x4(af[mt], sA + (a_row + mt * 16) * (TPAD * 2) + ks * 32 + a_kb);
#pragma unroll
            for (int np = 0; np < 4; np++) {
                uint32_t off = (b_row + np * 16) * (TPAD * 2) + ks * 32 + b_kb;
                ldm_x4(bk[np], sBk + off);
                ldm_x4(bv[np], sBv + off);
            }
#pragma unroll
            for (int mt = 0; mt < 2; mt++)
#pragma unroll
                for (int np = 0; np < 4; np++) {
                    mma_h32(accK[mt][2 * np],     af[mt], bk[np]);
                    mma_h32(accK[mt][2 * np + 1], af[mt], bk[np] + 2);
                    mma_h32(accV[mt][2 * np],     af[mt], bv[np]);
                    mma_h32(accV[mt][2 * np + 1], af[mt], bv[np] + 2);
                }
        }
    }

    // ---- attention epilogue: warp owns rows wr*32..+31, head cols wc*64..+63
    float dp[4] = {0, 0, 0, 0}, qn2[4] = {0, 0, 0, 0}, kn2[4] = {0, 0, 0, 0};
    int rbase = m0 + wr * 32 + (l >> 2);
    int qrow[4];
#pragma unroll
    for (int p = 0; p < 4; p++) qrow[p] = g_rep2[rbase + p * 8];

#pragma unroll
    for (int mt = 0; mt < 2; mt++)
#pragma unroll
        for (int nt = 0; nt < 8; nt++) {
            int col = wc * 64 + nt * 8 + 2 * (l & 3);
            float kb0 = kb_s[col], kb1 = kb_s[col + 1];
#pragma unroll
            for (int h = 0; h < 2; h++) {            // h=0: rows l>>2 ; h=1: +8
                int p = mt * 2 + h;
                float k0 = accK[mt][nt][2 * h]     + kb0;
                float k1 = accK[mt][nt][2 * h + 1] + kb1;
                float2 qf = __half22float2(*reinterpret_cast<const __half2*>(
                    g_xq + (size_t)qrow[p] * HID + n0 + col));
                dp[p]  += qf.x * k0 + qf.y * k1;
                qn2[p] += qf.x * qf.x + qf.y * qf.y;
                kn2[p] += k0 * k0 + k1 * k1;
            }
        }
#pragma unroll
    for (int o = 1; o <= 2; o <<= 1)
#pragma unroll
        for (int p = 0; p < 4; p++) {
            dp[p]  += __shfl_xor_sync(0xffffffffu, dp[p],  o);
            qn2[p] += __shfl_xor_sync(0xffffffffu, qn2[p], o);
            kn2[p] += __shfl_xor_sync(0xffffffffu, kn2[p], o);
        }
    float att[4];
#pragma unroll
    for (int p = 0; p < 4; p++)
        att[p] = dp[p] / (fmaxf(sqrtf(qn2[p]), EPS) * fmaxf(sqrtf(kn2[p]), EPS));

#pragma unroll
    for (int mt = 0; mt < 2; mt++)
#pragma unroll
        for (int nt = 0; nt < 8; nt++) {
            int col = wc * 64 + nt * 8 + 2 * (l & 3);
            float vb0 = vb_s[col], vb1 = vb_s[col + 1];
#pragma unroll
            for (int h = 0; h < 2; h++) {
                int p = mt * 2 + h;
                int grow = rbase + mt * 16 + h * 8;
                const float2 xv = *reinterpret_cast<const float2*>(
                    x + (size_t)grow * HID + n0 + col);
                float2 o;
                o.x = xv.x + (accV[mt][nt][2 * h]     + vb0) * att[p];
                o.y = xv.y + (accV[mt][nt][2 * h + 1] + vb1) * att[p];
                *reinterpret_cast<float2*>(out + (size_t)grow * HID + n0 + col) = o;
            }
        }
}

// ---------------- launch -----------------------------------------------------
extern "C" void kernel_launch(void* const* d_in, const int* in_sizes, int n_in,
                              void* d_out, int out_size) {
    const float* x    = (const float*)d_in[0];
    const float* y    = (const float*)d_in[1];
    const int*   rep  = (const int*)d_in[2];
    const float* ln_w = (const float*)d_in[3];
    const float* q_w  = (const float*)d_in[4];
    const float* q_b  = (const float*)d_in[5];
    const float* k_w  = (const float*)d_in[6];
    const float* k_b  = (const float*)d_in[7];
    const float* v_w  = (const float*)d_in[8];
    const float* v_b  = (const float*)d_in[9];
    float* out = (float*)d_out;

    cudaFuncSetAttribute(k_gemm_q,  cudaFuncAttributeMaxDynamicSharedMemorySize, SMEM_Q);
    cudaFuncSetAttribute(k_gemm_kv, cudaFuncAttributeMaxDynamicSharedMemorySize, SMEM_KV);

    // row compaction
    k_zero<<<16, 1024>>>();
    k_mark<<<64, 1024>>>(rep);
    k_scan<<<1, 1024>>>();
    k_remap<<<64, 1024>>>(rep);

    // prep
    k_rmsnorm<<<NROWS / 8, 256>>>(x, ln_w);
    k_convert_y<<<NROWS * HID / 4 / 256, 256>>>(y);
    k_convert_w<<<3 * HID * HID / 4 / 256, 256>>>(q_w, k_w, v_w);

    dim3 grid(HID / 128, NROWS / 128);      // (8, 512)
    k_gemm_q<<<grid, 256, SMEM_Q>>>(q_b);
    k_gemm_kv<<<grid, 256, SMEM_KV>>>(x, k_b, v_b, out);
}

// round 10
// speedup vs baseline: 3.2216x; 1.6172x over previous
#include <cuda_runtime.h>
#include <cuda_fp16.h>
#include <cstdint>

// ============================================================================
// ResAttentionBlock (ptxas target sm_103 rejects tcgen05 -> legacy mma.sync).
// R10: revert to R6 floor structure (3-stage, 256thr, 1 CTA/SM) with fp16
//      (f32 acc, same rt=16, 4x less quant error), and fold the y->fp16
//      conversion INTO k_gemm_q (issue-bound kernel, idle memory pipes),
//      software-pipelined so the f32 loads never stall HMMA issue.
// ============================================================================

#define EPS 1e-6f
constexpr int NROWS = 65536;
constexpr int HID   = 1024;
constexpr int KC    = 64;              // k-chunk (elements)
constexpr int NCH   = HID / KC;        // 16
constexpr int TPAD  = 72;              // padded row stride in fp16 elems (144B)
constexpr int TILE_B = 128 * TPAD * 2; // one 128x64 fp16 tile = 18432 B
constexpr int STG   = 3;               // pipeline stages

constexpr int SMEM_Q  = 512  + STG * 2 * TILE_B;   // 111104
constexpr int SMEM_KV = 1024 + STG * 3 * TILE_B;   // 166912

// ---------------- scratch (device globals; no allocation allowed) -----------
__device__ __align__(16) __half g_h [67108864];
__device__ __align__(16) __half g_yb[67108864];
__device__ __align__(16) __half g_xq[67108864];
__device__ __align__(16) __half g_wq[1048576];
__device__ __align__(16) __half g_wk[1048576];
__device__ __align__(16) __half g_wv[1048576];
__device__ __align__(16) int g_list[NROWS];     // compacted -> original row
__device__ __align__(16) int g_pos [NROWS];     // original row -> compacted
__device__ __align__(16) int g_rep2[NROWS];     // pos[rep[i]]
__device__ __align__(16) unsigned char g_flag[NROWS];
__device__ int g_cnt[2];                         // [0]=count, [1]=padded

// ---------------- helpers ----------------------------------------------------
__device__ __forceinline__ uint32_t smem_u32(const void* p) {
    uint32_t a;
    asm("{ .reg .u64 t; cvta.to.shared.u64 t, %1; cvt.u32.u64 %0, t; }" : "=r"(a) : "l"(p));
    return a;
}
__device__ __forceinline__ void cp_async16(uint32_t dst, const void* src) {
    asm volatile("cp.async.cg.shared.global [%0], [%1], 16;" :: "r"(dst), "l"(src) : "memory");
}
#define CP_COMMIT() asm volatile("cp.async.commit_group;" ::: "memory")
#define CP_WAIT(n)  asm volatile("cp.async.wait_group %0;" :: "n"(n) : "memory")

__device__ __forceinline__ void ldm_x4(uint32_t* r, uint32_t addr) {
    asm volatile("ldmatrix.sync.aligned.m8n8.x4.shared.b16 {%0,%1,%2,%3}, [%4];"
                 : "=r"(r[0]), "=r"(r[1]), "=r"(r[2]), "=r"(r[3]) : "r"(addr));
}
__device__ __forceinline__ void mma_h32(float* d, const uint32_t* a, const uint32_t* b) {
    asm volatile(
        "mma.sync.aligned.m16n8k16.row.col.f32.f16.f16.f32 "
        "{%0,%1,%2,%3}, {%4,%5,%6,%7}, {%8,%9}, {%0,%1,%2,%3};"
        : "+f"(d[0]), "+f"(d[1]), "+f"(d[2]), "+f"(d[3])
        : "r"(a[0]), "r"(a[1]), "r"(a[2]), "r"(a[3]), "r"(b[0]), "r"(b[1]));
}
__device__ __forceinline__ uint2 f4_to_h2x2(float4 v) {
    __half2 p0 = __floats2half2_rn(v.x, v.y);
    __half2 p1 = __floats2half2_rn(v.z, v.w);
    uint2 s;
    s.x = *reinterpret_cast<uint32_t*>(&p0);
    s.y = *reinterpret_cast<uint32_t*>(&p1);
    return s;
}

// Load one 128-row x 64-col fp16 tile into padded smem (stride 144B). 256 thr.
__device__ __forceinline__ void load_tile(uint32_t sbase, const __half* __restrict__ g,
                                          int row0, int col0) {
    const int tid = threadIdx.x;
#pragma unroll
    for (int k = 0; k < 4; k++) {
        int u = tid + k * 256;              // 1024 16B units (8 per row)
        int r = u >> 3, c = u & 7;
        cp_async16(sbase + r * (TPAD * 2) + c * 16,
                   g + (size_t)(row0 + r) * HID + col0 + c * 8);
    }
}

// ---------------- compaction kernels -----------------------------------------
__global__ void __launch_bounds__(1024) k_zero() {
    reinterpret_cast<int*>(g_flag)[blockIdx.x * 1024 + threadIdx.x] = 0;
}
__global__ void __launch_bounds__(1024) k_mark(const int* __restrict__ rep) {
    g_flag[rep[blockIdx.x * 1024 + threadIdx.x]] = 1;   // idempotent race
}
__global__ void __launch_bounds__(1024) k_scan() {      // single CTA
    __shared__ int wsum[32];
    int t = threadIdx.x, lane = t & 31, w = t >> 5;
    int base = t * 64;
    int s = 0;
#pragma unroll 8
    for (int j = 0; j < 64; j++) s += g_flag[base + j];
    int v = s;
#pragma unroll
    for (int o = 1; o < 32; o <<= 1) {
        int u = __shfl_up_sync(0xffffffffu, v, o);
        if (lane >= o) v += u;
    }
    if (lane == 31) wsum[w] = v;
    __syncthreads();
    if (w == 0) {
        int x2 = wsum[lane];
#pragma unroll
        for (int o = 1; o < 32; o <<= 1) {
            int u = __shfl_up_sync(0xffffffffu, x2, o);
            if (lane >= o) x2 += u;
        }
        wsum[lane] = x2;
    }
    __syncthreads();
    int excl = v - s + (w ? wsum[w - 1] : 0);
    int idx = excl;
    for (int j = 0; j < 64; j++) {
        int r = base + j;
        if (g_flag[r]) { g_list[idx] = r; g_pos[r] = idx; idx++; }
    }
    if (t == 1023) {
        int tot = excl + s;
        g_cnt[0] = tot;
        g_cnt[1] = (tot + 127) & ~127;
    }
}
__global__ void __launch_bounds__(1024) k_remap(const int* __restrict__ rep) {
    int i = blockIdx.x * 1024 + threadIdx.x;
    g_rep2[i] = g_pos[rep[i]];
}

// ---------------- prep kernels -----------------------------------------------
__global__ void __launch_bounds__(256) k_rmsnorm(const float* __restrict__ x,
                                                 const float* __restrict__ w) {
    int ci   = (blockIdx.x * 256 + threadIdx.x) >> 5;
    int lane = threadIdx.x & 31;
    int cnt = g_cnt[0], cpad = g_cnt[1];
    if (ci >= cpad) return;
    uint2* hp = reinterpret_cast<uint2*>(g_h + (size_t)ci * HID);
    if (ci >= cnt) {
        uint2 z = make_uint2(0u, 0u);
#pragma unroll
        for (int i = 0; i < 8; i++) hp[lane + i * 32] = z;
        return;
    }
    int row = g_list[ci];
    const float4* xp = reinterpret_cast<const float4*>(x + (size_t)row * HID);
    float4 v[8];
    float ss = 0.f;
#pragma unroll
    for (int i = 0; i < 8; i++) {
        v[i] = xp[lane + i * 32];
        ss += v[i].x * v[i].x + v[i].y * v[i].y + v[i].z * v[i].z + v[i].w * v[i].w;
    }
#pragma unroll
    for (int o = 16; o > 0; o >>= 1) ss += __shfl_xor_sync(0xffffffffu, ss, o);
    float rs = rsqrtf(ss * (1.0f / HID) + EPS);
    const float4* wp = reinterpret_cast<const float4*>(w);
#pragma unroll
    for (int i = 0; i < 8; i++) {
        float4 wv = wp[lane + i * 32];
        float4 t = make_float4(v[i].x * rs * wv.x, v[i].y * rs * wv.y,
                               v[i].z * rs * wv.z, v[i].w * rs * wv.w);
        hp[lane + i * 32] = f4_to_h2x2(t);
    }
}

__global__ void __launch_bounds__(256) k_convert_w(const float* __restrict__ qw,
                                                   const float* __restrict__ kw,
                                                   const float* __restrict__ vw) {
    int which = blockIdx.x >> 10;
    int i = (blockIdx.x & 1023) * 256 + threadIdx.x;
    const float* src = (which == 0) ? qw : (which == 1) ? kw : vw;
    __half* dst = (which == 0) ? g_wq : (which == 1) ? g_wk : g_wv;
    float4 v = reinterpret_cast<const float4*>(src)[i];
    reinterpret_cast<uint2*>(dst)[i] = f4_to_h2x2(v);
}

// ---- GEMM-Q (+ fused y->fp16 conversion): 256 thr, 32x64 warp, 3-stage ------
__global__ void __launch_bounds__(256, 1) k_gemm_q(const float* __restrict__ qb,
                                                   const float* __restrict__ y) {
    const int n0 = blockIdx.x * 128, m0 = blockIdx.y * 128;
    const int tid = threadIdx.x;
    // y conversion slice: 4096 CTAs x 16 rows; 256 float4 per chunk step
    const int cid = blockIdx.y * 8 + blockIdx.x;
    const float4* yf4 = reinterpret_cast<const float4*>(y);
    uint2* yh2 = reinterpret_cast<uint2*>(g_yb);
    const size_t ybase = (size_t)cid * 4096 + tid;

    if (m0 >= g_cnt[1]) {                   // inactive tile: convert slice, exit
#pragma unroll 4
        for (int ci = 0; ci < NCH; ci++)
            yh2[ybase + ci * 256] = f4_to_h2x2(yf4[ybase + ci * 256]);
        return;
    }

    extern __shared__ char smem[];
    const int w = tid >> 5, l = tid & 31;
    const int wr = w >> 1, wc = w & 1;      // warp grid 4x2, warp tile 32x64
    float* qb_s = reinterpret_cast<float*>(smem);
    uint32_t sb = smem_u32(smem) + 512;

    if (tid < 128) qb_s[tid] = qb[n0 + tid];
    load_tile(sb,                       g_h,  m0, 0);
    load_tile(sb + TILE_B,              g_wq, n0, 0);
    CP_COMMIT();
    load_tile(sb + 2 * TILE_B,          g_h,  m0, KC);
    load_tile(sb + 2 * TILE_B + TILE_B, g_wq, n0, KC);
    CP_COMMIT();

    float4 yv = yf4[ybase];                 // conversion pipeline: preload pos 0

    float acc[2][8][4];
#pragma unroll
    for (int mt = 0; mt < 2; mt++)
#pragma unroll
        for (int nt = 0; nt < 8; nt++)
#pragma unroll
            for (int i = 0; i < 4; i++) acc[mt][nt][i] = 0.f;

    const int a_row = wr * 32 + (l & 7) + ((l >> 3) & 1) * 8;
    const int a_kb  = (l >> 4) * 16;
    const int b_row = wc * 64 + ((l >> 4) & 1) * 8 + (l & 7);
    const int b_kb  = ((l >> 3) & 1) * 16;

    for (int ci = 0; ci < NCH; ci++) {
        CP_WAIT(1);                 // chunk ci resident
        __syncthreads();
        if (ci + 2 < NCH) {
            uint32_t tb = sb + (uint32_t)((ci + 2) % STG) * (2 * TILE_B);
            load_tile(tb,          g_h,  m0, (ci + 2) * KC);
            load_tile(tb + TILE_B, g_wq, n0, (ci + 2) * KC);
        }
        CP_COMMIT();                // always commit (uniform group counting)

        // y conversion: store value loaded ~1 chunk ago, issue next load
        {
            float4 ynext;
            if (ci + 1 < NCH) ynext = yf4[ybase + (size_t)(ci + 1) * 256];
            yh2[ybase + (size_t)ci * 256] = f4_to_h2x2(yv);
            yv = ynext;
        }

        uint32_t sA = sb + (uint32_t)(ci % STG) * (2 * TILE_B);
        uint32_t sB = sA + TILE_B;
#pragma unroll
        for (int ks = 0; ks < 4; ks++) {
            uint32_t af[2][4], bf[4][4];
#pragma unroll
            for (int mt = 0; mt < 2; mt++)
                ldm_x4(af[mt], sA + (a_row + mt * 16) * (TPAD * 2) + ks * 32 + a_kb);
#pragma unroll
            for (int np = 0; np < 4; np++)
                ldm_x4(bf[np], sB + (b_row + np * 16) * (TPAD * 2) + ks * 32 + b_kb);
#pragma unroll
            for (int mt = 0; mt < 2; mt++)
#pragma unroll
                for (int np = 0; np < 4; np++) {
                    mma_h32(acc[mt][2 * np],     af[mt], bf[np]);
                    mma_h32(acc[mt][2 * np + 1], af[mt], bf[np] + 2);
                }
        }
    }

    // epilogue: +bias, fp16, store
#pragma unroll
    for (int mt = 0; mt < 2; mt++)
#pragma unroll
        for (int nt = 0; nt < 8; nt++) {
            int col = wc * 64 + nt * 8 + 2 * (l & 3);
            float b0 = qb_s[col], b1 = qb_s[col + 1];
            int r0 = m0 + wr * 32 + mt * 16 + (l >> 2);
            __half2 p0 = __floats2half2_rn(acc[mt][nt][0] + b0, acc[mt][nt][1] + b1);
            __half2 p1 = __floats2half2_rn(acc[mt][nt][2] + b0, acc[mt][nt][3] + b1);
            *reinterpret_cast<__half2*>(g_xq + (size_t)r0 * HID + n0 + col) = p0;
            *reinterpret_cast<__half2*>(g_xq + (size_t)(r0 + 8) * HID + n0 + col) = p1;
        }
}

// ---------------- fused GEMM-KV + attention epilogue: 3-stage pipe -----------
__global__ void __launch_bounds__(256, 1) k_gemm_kv(const float* __restrict__ x,
                                                    const float* __restrict__ kb,
                                                    const float* __restrict__ vb,
                                                    float* __restrict__ out) {
    extern __shared__ char smem[];
    const int tid = threadIdx.x, w = tid >> 5, l = tid & 31;
    const int wr = w >> 1, wc = w & 1;
    const int n0 = blockIdx.x * 128, m0 = blockIdx.y * 128;
    float* kb_s = reinterpret_cast<float*>(smem);
    float* vb_s = kb_s + 128;
    uint32_t sb = smem_u32(smem) + 1024;

    if (tid < 128) { kb_s[tid] = kb[n0 + tid]; vb_s[tid] = vb[n0 + tid]; }
    load_tile(sb,                           g_yb, m0, 0);
    load_tile(sb + TILE_B,                  g_wk, n0, 0);
    load_tile(sb + 2 * TILE_B,              g_wv, n0, 0);
    CP_COMMIT();
    load_tile(sb + 3 * TILE_B,              g_yb, m0, KC);
    load_tile(sb + 3 * TILE_B + TILE_B,     g_wk, n0, KC);
    load_tile(sb + 3 * TILE_B + 2 * TILE_B, g_wv, n0, KC);
    CP_COMMIT();

    float accK[2][8][4], accV[2][8][4];
#pragma unroll
    for (int mt = 0; mt < 2; mt++)
#pragma unroll
        for (int nt = 0; nt < 8; nt++)
#pragma unroll
            for (int i = 0; i < 4; i++) { accK[mt][nt][i] = 0.f; accV[mt][nt][i] = 0.f; }

    const int a_row = wr * 32 + (l & 7) + ((l >> 3) & 1) * 8;
    const int a_kb  = (l >> 4) * 16;
    const int b_row = wc * 64 + ((l >> 4) & 1) * 8 + (l & 7);
    const int b_kb  = ((l >> 3) & 1) * 16;

    for (int ci = 0; ci < NCH; ci++) {
        CP_WAIT(1);
        __syncthreads();
        if (ci + 2 < NCH) {
            uint32_t tb = sb + (uint32_t)((ci + 2) % STG) * (3 * TILE_B);
            load_tile(tb,              g_yb, m0, (ci + 2) * KC);
            load_tile(tb + TILE_B,     g_wk, n0, (ci + 2) * KC);
            load_tile(tb + 2 * TILE_B, g_wv, n0, (ci + 2) * KC);
        }
        CP_COMMIT();

        uint32_t sA  = sb + (uint32_t)(ci % STG) * (3 * TILE_B);
        uint32_t sBk = sA + TILE_B;
        uint32_t sBv = sA + 2 * TILE_B;
#pragma unroll
        for (int ks = 0; ks < 4; ks++) {
            uint32_t af[2][4], bk[4][4], bv[4][4];
#pragma unroll
            for (int mt = 0; mt < 2; mt++)
                ldm_x4(af[mt], sA + (a_row + mt * 16) * (TPAD * 2) + ks * 32 + a_kb);
#pragma unroll
            for (int np = 0; np < 4; np++) {
                uint32_t off = (b_row + np * 16) * (TPAD * 2) + ks * 32 + b_kb;
                ldm_x4(bk[np], sBk + off);
                ldm_x4(bv[np], sBv + off);
            }
#pragma unroll
            for (int mt = 0; mt < 2; mt++)
#pragma unroll
                for (int np = 0; np < 4; np++) {
                    mma_h32(accK[mt][2 * np],     af[mt], bk[np]);
                    mma_h32(accK[mt][2 * np + 1], af[mt], bk[np] + 2);
                    mma_h32(accV[mt][2 * np],     af[mt], bv[np]);
                    mma_h32(accV[mt][2 * np + 1], af[mt], bv[np] + 2);
                }
        }
    }

    // ---- attention epilogue: warp owns rows wr*32..+31, head cols wc*64..+63
    float dp[4] = {0, 0, 0, 0}, qn2[4] = {0, 0, 0, 0}, kn2[4] = {0, 0, 0, 0};
    int rbase = m0 + wr * 32 + (l >> 2);
    int qrow[4];
#pragma unroll
    for (int p = 0; p < 4; p++) qrow[p] = g_rep2[rbase + p * 8];

#pragma unroll
    for (int mt = 0; mt < 2; mt++)
#pragma unroll
        for (int nt = 0; nt < 8; nt++) {
            int col = wc * 64 + nt * 8 + 2 * (l & 3);
            float kb0 = kb_s[col], kb1 = kb_s[col + 1];
#pragma unroll
            for (int h = 0; h < 2; h++) {            // h=0: rows l>>2 ; h=1: +8
                int p = mt * 2 + h;
                float k0 = accK[mt][nt][2 * h]     + kb0;
                float k1 = accK[mt][nt][2 * h + 1] + kb1;
                float2 qf = __half22float2(*reinterpret_cast<const __half2*>(
                    g_xq + (size_t)qrow[p] * HID + n0 + col));
                dp[p]  += qf.x * k0 + qf.y * k1;
                qn2[p] += qf.x * qf.x + qf.y * qf.y;
                kn2[p] += k0 * k0 + k1 * k1;
            }
        }
#pragma unroll
    for (int o = 1; o <= 2; o <<= 1)
#pragma unroll
        for (int p = 0; p < 4; p++) {
            dp[p]  += __shfl_xor_sync(0xffffffffu, dp[p],  o);
            qn2[p] += __shfl_xor_sync(0xffffffffu, qn2[p], o);
            kn2[p] += __shfl_xor_sync(0xffffffffu, kn2[p], o);
        }
    float att[4];
#pragma unroll
    for (int p = 0; p < 4; p++)
        att[p] = dp[p] / (fmaxf(sqrtf(qn2[p]), EPS) * fmaxf(sqrtf(kn2[p]), EPS));

#pragma unroll
    for (int mt = 0; mt < 2; mt++)
#pragma unroll
        for (int nt = 0; nt < 8; nt++) {
            int col = wc * 64 + nt * 8 + 2 * (l & 3);
            float vb0 = vb_s[col], vb1 = vb_s[col + 1];
#pragma unroll
            for (int h = 0; h < 2; h++) {
                int p = mt * 2 + h;
                int grow = rbase + mt * 16 + h * 8;
                const float2 xv = *reinterpret_cast<const float2*>(
                    x + (size_t)grow * HID + n0 + col);
                float2 o;
                o.x = xv.x + (accV[mt][nt][2 * h]     + vb0) * att[p];
                o.y = xv.y + (accV[mt][nt][2 * h + 1] + vb1) * att[p];
                *reinterpret_cast<float2*>(out + (size_t)grow * HID + n0 + col) = o;
            }
        }
}

// ---------------- launch -----------------------------------------------------
extern "C" void kernel_launch(void* const* d_in, const int* in_sizes, int n_in,
                              void* d_out, int out_size) {
    const float* x    = (const float*)d_in[0];
    const float* y    = (const float*)d_in[1];
    const int*   rep  = (const int*)d_in[2];
    const float* ln_w = (const float*)d_in[3];
    const float* q_w  = (const float*)d_in[4];
    const float* q_b  = (const float*)d_in[5];
    const float* k_w  = (const float*)d_in[6];
    const float* k_b  = (const float*)d_in[7];
    const float* v_w  = (const float*)d_in[8];
    const float* v_b  = (const float*)d_in[9];
    float* out = (float*)d_out;

    cudaFuncSetAttribute(k_gemm_q,  cudaFuncAttributeMaxDynamicSharedMemorySize, SMEM_Q);
    cudaFuncSetAttribute(k_gemm_kv, cudaFuncAttributeMaxDynamicSharedMemorySize, SMEM_KV);

    // row compaction
    k_zero<<<16, 1024>>>();
    k_mark<<<64, 1024>>>(rep);
    k_scan<<<1, 1024>>>();
    k_remap<<<64, 1024>>>(rep);

    // prep (y conversion is fused into k_gemm_q)
    k_rmsnorm<<<NROWS / 8, 256>>>(x, ln_w);
    k_convert_w<<<3 * HID * HID / 4 / 256, 256>>>(q_w, k_w, v_w);

    dim3 grid(HID / 128, NROWS / 128);      // (8, 512)
    k_gemm_q<<<grid, 256, SMEM_Q>>>(q_b, y);
    k_gemm_kv<<<grid, 256, SMEM_KV>>>(x, k_b, v_b, out);
}

// round 11
// speedup vs baseline: 3.2514x; 1.0093x over previous
#include <cuda_runtime.h>
#include <cuda_fp16.h>
#include <cstdint>

// ============================================================================
// ResAttentionBlock (ptxas target sm_103 rejects tcgen05 -> legacy mma.sync).
// R11: R10 structure (proven at the HMMA issue floor) + prep consolidation:
//      - k_zero deleted (BSS zero-init; flags cleared post-scan in k_prep)
//      - remap + flag-clear + 3 weight conversions fused into k_prep
//      Pipeline: mark -> scan -> prep -> gemm_q(+y cvt) -> gemm_kv(+attention)
// ============================================================================

#define EPS 1e-6f
constexpr int NROWS = 65536;
constexpr int HID   = 1024;
constexpr int KC    = 64;              // k-chunk (elements)
constexpr int NCH   = HID / KC;        // 16
constexpr int TPAD  = 72;              // padded row stride in fp16 elems (144B)
constexpr int TILE_B = 128 * TPAD * 2; // one 128x64 fp16 tile = 18432 B
constexpr int STG   = 3;               // pipeline stages

constexpr int SMEM_Q  = 512  + STG * 2 * TILE_B;   // 111104
constexpr int SMEM_KV = 1024 + STG * 3 * TILE_B;   // 166912

// k_prep grid partition
constexpr int PREP_RMS  = 8192;                    // rmsnorm: 8 rows/CTA
constexpr int PREP_W    = 3072;                    // 3 weights x 1024 CTAs
constexpr int PREP_RMAP = 256;                     // remap: 256 rows/CTA
constexpr int PREP_FLAG = 64;                      // flag clear
constexpr int PREP_GRID = PREP_RMS + PREP_W + PREP_RMAP + PREP_FLAG;

// ---------------- scratch (device globals; no allocation allowed) -----------
__device__ __align__(16) __half g_h [67108864];
__device__ __align__(16) __half g_yb[67108864];
__device__ __align__(16) __half g_xq[67108864];
__device__ __align__(16) __half g_wq[1048576];
__device__ __align__(16) __half g_wk[1048576];
__device__ __align__(16) __half g_wv[1048576];
__device__ __align__(16) int g_list[NROWS];     // compacted -> original row
__device__ __align__(16) int g_pos [NROWS];     // original row -> compacted
__device__ __align__(16) int g_rep2[NROWS];     // pos[rep[i]]
__device__ __align__(16) unsigned char g_flag[NROWS];   // BSS zero-initialized
__device__ int g_cnt[2];                         // [0]=count, [1]=padded

// ---------------- helpers ----------------------------------------------------
__device__ __forceinline__ uint32_t smem_u32(const void* p) {
    uint32_t a;
    asm("{ .reg .u64 t; cvta.to.shared.u64 t, %1; cvt.u32.u64 %0, t; }" : "=r"(a) : "l"(p));
    return a;
}
__device__ __forceinline__ void cp_async16(uint32_t dst, const void* src) {
    asm volatile("cp.async.cg.shared.global [%0], [%1], 16;" :: "r"(dst), "l"(src) : "memory");
}
#define CP_COMMIT() asm volatile("cp.async.commit_group;" ::: "memory")
#define CP_WAIT(n)  asm volatile("cp.async.wait_group %0;" :: "n"(n) : "memory")

__device__ __forceinline__ void ldm_x4(uint32_t* r, uint32_t addr) {
    asm volatile("ldmatrix.sync.aligned.m8n8.x4.shared.b16 {%0,%1,%2,%3}, [%4];"
                 : "=r"(r[0]), "=r"(r[1]), "=r"(r[2]), "=r"(r[3]) : "r"(addr));
}
__device__ __forceinline__ void mma_h32(float* d, const uint32_t* a, const uint32_t* b) {
    asm volatile(
        "mma.sync.aligned.m16n8k16.row.col.f32.f16.f16.f32 "
        "{%0,%1,%2,%3}, {%4,%5,%6,%7}, {%8,%9}, {%0,%1,%2,%3};"
        : "+f"(d[0]), "+f"(d[1]), "+f"(d[2]), "+f"(d[3])
        : "r"(a[0]), "r"(a[1]), "r"(a[2]), "r"(a[3]), "r"(b[0]), "r"(b[1]));
}
__device__ __forceinline__ uint2 f4_to_h2x2(float4 v) {
    __half2 p0 = __floats2half2_rn(v.x, v.y);
    __half2 p1 = __floats2half2_rn(v.z, v.w);
    uint2 s;
    s.x = *reinterpret_cast<uint32_t*>(&p0);
    s.y = *reinterpret_cast<uint32_t*>(&p1);
    return s;
}

// Load one 128-row x 64-col fp16 tile into padded smem (stride 144B). 256 thr.
__device__ __forceinline__ void load_tile(uint32_t sbase, const __half* __restrict__ g,
                                          int row0, int col0) {
    const int tid = threadIdx.x;
#pragma unroll
    for (int k = 0; k < 4; k++) {
        int u = tid + k * 256;              // 1024 16B units (8 per row)
        int r = u >> 3, c = u & 7;
        cp_async16(sbase + r * (TPAD * 2) + c * 16,
                   g + (size_t)(row0 + r) * HID + col0 + c * 8);
    }
}

// ---------------- compaction kernels -----------------------------------------
__global__ void __launch_bounds__(1024) k_mark(const int* __restrict__ rep) {
    g_flag[rep[blockIdx.x * 1024 + threadIdx.x]] = 1;   // idempotent race
}
__global__ void __launch_bounds__(1024) k_scan() {      // single CTA
    __shared__ int wsum[32];
    int t = threadIdx.x, lane = t & 31, w = t >> 5;
    int base = t * 64;
    int s = 0;
#pragma unroll 8
    for (int j = 0; j < 64; j++) s += g_flag[base + j];
    int v = s;
#pragma unroll
    for (int o = 1; o < 32; o <<= 1) {
        int u = __shfl_up_sync(0xffffffffu, v, o);
        if (lane >= o) v += u;
    }
    if (lane == 31) wsum[w] = v;
    __syncthreads();
    if (w == 0) {
        int x2 = wsum[lane];
#pragma unroll
        for (int o = 1; o < 32; o <<= 1) {
            int u = __shfl_up_sync(0xffffffffu, x2, o);
            if (lane >= o) x2 += u;
        }
        wsum[lane] = x2;
    }
    __syncthreads();
    int excl = v - s + (w ? wsum[w - 1] : 0);
    int idx = excl;
    for (int j = 0; j < 64; j++) {
        int r = base + j;
        if (g_flag[r]) { g_list[idx] = r; g_pos[r] = idx; idx++; }
    }
    if (t == 1023) {
        int tot = excl + s;
        g_cnt[0] = tot;
        g_cnt[1] = (tot + 127) & ~127;
    }
}

// ---- fused prep: rmsnorm | weight converts | remap | flag clear -------------
__global__ void __launch_bounds__(256) k_prep(const float* __restrict__ x,
                                              const float* __restrict__ lnw,
                                              const float* __restrict__ qw,
                                              const float* __restrict__ kw,
                                              const float* __restrict__ vw,
                                              const int* __restrict__ rep) {
    const int b = blockIdx.x, tid = threadIdx.x;

    if (b < PREP_RMS) {
        // -------- rmsnorm over compacted rows
        int ci   = (b * 256 + tid) >> 5;
        int lane = tid & 31;
        int cnt = g_cnt[0], cpad = g_cnt[1];
        if (ci >= cpad) return;
        uint2* hp = reinterpret_cast<uint2*>(g_h + (size_t)ci * HID);
        if (ci >= cnt) {
            uint2 z = make_uint2(0u, 0u);
#pragma unroll
            for (int i = 0; i < 8; i++) hp[lane + i * 32] = z;
            return;
        }
        int row = g_list[ci];
        const float4* xp = reinterpret_cast<const float4*>(x + (size_t)row * HID);
        float4 v[8];
        float ss = 0.f;
#pragma unroll
        for (int i = 0; i < 8; i++) {
            v[i] = xp[lane + i * 32];
            ss += v[i].x * v[i].x + v[i].y * v[i].y + v[i].z * v[i].z + v[i].w * v[i].w;
        }
#pragma unroll
        for (int o = 16; o > 0; o >>= 1) ss += __shfl_xor_sync(0xffffffffu, ss, o);
        float rs = rsqrtf(ss * (1.0f / HID) + EPS);
        const float4* wp = reinterpret_cast<const float4*>(lnw);
#pragma unroll
        for (int i = 0; i < 8; i++) {
            float4 wv = wp[lane + i * 32];
            float4 t = make_float4(v[i].x * rs * wv.x, v[i].y * rs * wv.y,
                                   v[i].z * rs * wv.z, v[i].w * rs * wv.w);
            hp[lane + i * 32] = f4_to_h2x2(t);
        }
    } else if (b < PREP_RMS + PREP_W) {
        // -------- weight conversions (q, k, v)
        int j = b - PREP_RMS;
        int which = j >> 10;
        int i = (j & 1023) * 256 + tid;
        const float* src = (which == 0) ? qw : (which == 1) ? kw : vw;
        __half* dst = (which == 0) ? g_wq : (which == 1) ? g_wk : g_wv;
        float4 v = reinterpret_cast<const float4*>(src)[i];
        reinterpret_cast<uint2*>(dst)[i] = f4_to_h2x2(v);
    } else if (b < PREP_RMS + PREP_W + PREP_RMAP) {
        // -------- remap rep -> compacted positions
        int i = (b - PREP_RMS - PREP_W) * 256 + tid;
        g_rep2[i] = g_pos[rep[i]];
    } else {
        // -------- clear flags for the next replay (scan already consumed them)
        int i = (b - PREP_RMS - PREP_W - PREP_RMAP) * 256 + tid;
        reinterpret_cast<int*>(g_flag)[i] = 0;
    }
}

// ---- GEMM-Q (+ fused y->fp16 conversion): 256 thr, 32x64 warp, 3-stage ------
__global__ void __launch_bounds__(256, 1) k_gemm_q(const float* __restrict__ qb,
                                                   const float* __restrict__ y) {
    const int n0 = blockIdx.x * 128, m0 = blockIdx.y * 128;
    const int tid = threadIdx.x;
    // y conversion slice: 4096 CTAs x 16 rows; 256 float4 per chunk step
    const int cid = blockIdx.y * 8 + blockIdx.x;
    const float4* yf4 = reinterpret_cast<const float4*>(y);
    uint2* yh2 = reinterpret_cast<uint2*>(g_yb);
    const size_t ybase = (size_t)cid * 4096 + tid;

    if (m0 >= g_cnt[1]) {                   // inactive tile: convert slice, exit
#pragma unroll 4
        for (int ci = 0; ci < NCH; ci++)
            yh2[ybase + ci * 256] = f4_to_h2x2(yf4[ybase + ci * 256]);
        return;
    }

    extern __shared__ char smem[];
    const int w = tid >> 5, l = tid & 31;
    const int wr = w >> 1, wc = w & 1;      // warp grid 4x2, warp tile 32x64
    float* qb_s = reinterpret_cast<float*>(smem);
    uint32_t sb = smem_u32(smem) + 512;

    if (tid < 128) qb_s[tid] = qb[n0 + tid];
    load_tile(sb,                       g_h,  m0, 0);
    load_tile(sb + TILE_B,              g_wq, n0, 0);
    CP_COMMIT();
    load_tile(sb + 2 * TILE_B,          g_h,  m0, KC);
    load_tile(sb + 2 * TILE_B + TILE_B, g_wq, n0, KC);
    CP_COMMIT();

    float4 yv = yf4[ybase];                 // conversion pipeline: preload pos 0

    float acc[2][8][4];
#pragma unroll
    for (int mt = 0; mt < 2; mt++)
#pragma unroll
        for (int nt = 0; nt < 8; nt++)
#pragma unroll
            for (int i = 0; i < 4; i++) acc[mt][nt][i] = 0.f;

    const int a_row = wr * 32 + (l & 7) + ((l >> 3) & 1) * 8;
    const int a_kb  = (l >> 4) * 16;
    const int b_row = wc * 64 + ((l >> 4) & 1) * 8 + (l & 7);
    const int b_kb  = ((l >> 3) & 1) * 16;

    for (int ci = 0; ci < NCH; ci++) {
        CP_WAIT(1);                 // chunk ci resident
        __syncthreads();
        if (ci + 2 < NCH) {
            uint32_t tb = sb + (uint32_t)((ci + 2) % STG) * (2 * TILE_B);
            load_tile(tb,          g_h,  m0, (ci + 2) * KC);
            load_tile(tb + TILE_B, g_wq, n0, (ci + 2) * KC);
        }
        CP_COMMIT();                // always commit (uniform group counting)

        // y conversion: store value loaded ~1 chunk ago, issue next load
        {
            float4 ynext;
            if (ci + 1 < NCH) ynext = yf4[ybase + (size_t)(ci + 1) * 256];
            yh2[ybase + (size_t)ci * 256] = f4_to_h2x2(yv);
            yv = ynext;
        }

        uint32_t sA = sb + (uint32_t)(ci % STG) * (2 * TILE_B);
        uint32_t sB = sA + TILE_B;
#pragma unroll
        for (int ks = 0; ks < 4; ks++) {
            uint32_t af[2][4], bf[4][4];
#pragma unroll
            for (int mt = 0; mt < 2; mt++)
                ldm_x4(af[mt], sA + (a_row + mt * 16) * (TPAD * 2) + ks * 32 + a_kb);
#pragma unroll
            for (int np = 0; np < 4; np++)
                ldm_x4(bf[np], sB + (b_row + np * 16) * (TPAD * 2) + ks * 32 + b_kb);
#pragma unroll
            for (int mt = 0; mt < 2; mt++)
#pragma unroll
                for (int np = 0; np < 4; np++) {
                    mma_h32(acc[mt][2 * np],     af[mt], bf[np]);
                    mma_h32(acc[mt][2 * np + 1], af[mt], bf[np] + 2);
                }
        }
    }

    // epilogue: +bias, fp16, store
#pragma unroll
    for (int mt = 0; mt < 2; mt++)
#pragma unroll
        for (int nt = 0; nt < 8; nt++) {
            int col = wc * 64 + nt * 8 + 2 * (l & 3);
            float b0 = qb_s[col], b1 = qb_s[col + 1];
            int r0 = m0 + wr * 32 + mt * 16 + (l >> 2);
            __half2 p0 = __floats2half2_rn(acc[mt][nt][0] + b0, acc[mt][nt][1] + b1);
            __half2 p1 = __floats2half2_rn(acc[mt][nt][2] + b0, acc[mt][nt][3] + b1);
            *reinterpret_cast<__half2*>(g_xq + (size_t)r0 * HID + n0 + col) = p0;
            *reinterpret_cast<__half2*>(g_xq + (size_t)(r0 + 8) * HID + n0 + col) = p1;
        }
}

// ---------------- fused GEMM-KV + attention epilogue: 3-stage pipe -----------
__global__ void __launch_bounds__(256, 1) k_gemm_kv(const float* __restrict__ x,
                                                    const float* __restrict__ kb,
                                                    const float* __restrict__ vb,
                                                    float* __restrict__ out) {
    extern __shared__ char smem[];
    const int tid = threadIdx.x, w = tid >> 5, l = tid & 31;
    const int wr = w >> 1, wc = w & 1;
    const int n0 = blockIdx.x * 128, m0 = blockIdx.y * 128;
    float* kb_s = reinterpret_cast<float*>(smem);
    float* vb_s = kb_s + 128;
    uint32_t sb = smem_u32(smem) + 1024;

    if (tid < 128) { kb_s[tid] = kb[n0 + tid]; vb_s[tid] = vb[n0 + tid]; }
    load_tile(sb,                           g_yb, m0, 0);
    load_tile(sb + TILE_B,                  g_wk, n0, 0);
    load_tile(sb + 2 * TILE_B,              g_wv, n0, 0);
    CP_COMMIT();
    load_tile(sb + 3 * TILE_B,              g_yb, m0, KC);
    load_tile(sb + 3 * TILE_B + TILE_B,     g_wk, n0, KC);
    load_tile(sb + 3 * TILE_B + 2 * TILE_B, g_wv, n0, KC);
    CP_COMMIT();

    float accK[2][8][4], accV[2][8][4];
#pragma unroll
    for (int mt = 0; mt < 2; mt++)
#pragma unroll
        for (int nt = 0; nt < 8; nt++)
#pragma unroll
            for (int i = 0; i < 4; i++) { accK[mt][nt][i] = 0.f; accV[mt][nt][i] = 0.f; }

    const int a_row = wr * 32 + (l & 7) + ((l >> 3) & 1) * 8;
    const int a_kb  = (l >> 4) * 16;
    const int b_row = wc * 64 + ((l >> 4) & 1) * 8 + (l & 7);
    const int b_kb  = ((l >> 3) & 1) * 16;

    for (int ci = 0; ci < NCH; ci++) {
        CP_WAIT(1);
        __syncthreads();
        if (ci + 2 < NCH) {
            uint32_t tb = sb + (uint32_t)((ci + 2) % STG) * (3 * TILE_B);
            load_tile(tb,              g_yb, m0, (ci + 2) * KC);
            load_tile(tb + TILE_B,     g_wk, n0, (ci + 2) * KC);
            load_tile(tb + 2 * TILE_B, g_wv, n0, (ci + 2) * KC);
        }
        CP_COMMIT();

        uint32_t sA  = sb + (uint32_t)(ci % STG) * (3 * TILE_B);
        uint32_t sBk = sA + TILE_B;
        uint32_t sBv = sA + 2 * TILE_B;
#pragma unroll
        for (int ks = 0; ks < 4; ks++) {
            uint32_t af[2][4], bk[4][4], bv[4][4];
#pragma unroll
            for (int mt = 0; mt < 2; mt++)
                ldm_x4(af[mt], sA + (a_row + mt * 16) * (TPAD * 2) + ks * 32 + a_kb);
#pragma unroll
            for (int np = 0; np < 4; np++) {
                uint32_t off = (b_row + np * 16) * (TPAD * 2) + ks * 32 + b_kb;
                ldm_x4(bk[np], sBk + off);
                ldm_x4(bv[np], sBv + off);
            }
#pragma unroll
            for (int mt = 0; mt < 2; mt++)
#pragma unroll
                for (int np = 0; np < 4; np++) {
                    mma_h32(accK[mt][2 * np],     af[mt], bk[np]);
                    mma_h32(accK[mt][2 * np + 1], af[mt], bk[np] + 2);
                    mma_h32(accV[mt][2 * np],     af[mt], bv[np]);
                    mma_h32(accV[mt][2 * np + 1], af[mt], bv[np] + 2);
                }
        }
    }

    // ---- attention epilogue: warp owns rows wr*32..+31, head cols wc*64..+63
    float dp[4] = {0, 0, 0, 0}, qn2[4] = {0, 0, 0, 0}, kn2[4] = {0, 0, 0, 0};
    int rbase = m0 + wr * 32 + (l >> 2);
    int qrow[4];
#pragma unroll
    for (int p = 0; p < 4; p++) qrow[p] = g_rep2[rbase + p * 8];

#pragma unroll
    for (int mt = 0; mt < 2; mt++)
#pragma unroll
        for (int nt = 0; nt < 8; nt++) {
            int col = wc * 64 + nt * 8 + 2 * (l & 3);
            float kb0 = kb_s[col], kb1 = kb_s[col + 1];
#pragma unroll
            for (int h = 0; h < 2; h++) {            // h=0: rows l>>2 ; h=1: +8
                int p = mt * 2 + h;
                float k0 = accK[mt][nt][2 * h]     + kb0;
                float k1 = accK[mt][nt][2 * h + 1] + kb1;
                float2 qf = __half22float2(*reinterpret_cast<const __half2*>(
                    g_xq + (size_t)qrow[p] * HID + n0 + col));
                dp[p]  += qf.x * k0 + qf.y * k1;
                qn2[p] += qf.x * qf.x + qf.y * qf.y;
                kn2[p] += k0 * k0 + k1 * k1;
            }
        }
#pragma unroll
    for (int o = 1; o <= 2; o <<= 1)
#pragma unroll
        for (int p = 0; p < 4; p++) {
            dp[p]  += __shfl_xor_sync(0xffffffffu, dp[p],  o);
            qn2[p] += __shfl_xor_sync(0xffffffffu, qn2[p], o);
            kn2[p] += __shfl_xor_sync(0xffffffffu, kn2[p], o);
        }
    float att[4];
#pragma unroll
    for (int p = 0; p < 4; p++)
        att[p] = dp[p] / (fmaxf(sqrtf(qn2[p]), EPS) * fmaxf(sqrtf(kn2[p]), EPS));

#pragma unroll
    for (int mt = 0; mt < 2; mt++)
#pragma unroll
        for (int nt = 0; nt < 8; nt++) {
            int col = wc * 64 + nt * 8 + 2 * (l & 3);
            float vb0 = vb_s[col], vb1 = vb_s[col + 1];
#pragma unroll
            for (int h = 0; h < 2; h++) {
                int p = mt * 2 + h;
                int grow = rbase + mt * 16 + h * 8;
                const float2 xv = *reinterpret_cast<const float2*>(
                    x + (size_t)grow * HID + n0 + col);
                float2 o;
                o.x = xv.x + (accV[mt][nt][2 * h]     + vb0) * att[p];
                o.y = xv.y + (accV[mt][nt][2 * h + 1] + vb1) * att[p];
                *reinterpret_cast<float2*>(out + (size_t)grow * HID + n0 + col) = o;
            }
        }
}

// ---------------- launch -----------------------------------------------------
extern "C" void kernel_launch(void* const* d_in, const int* in_sizes, int n_in,
                              void* d_out, int out_size) {
    const float* x    = (const float*)d_in[0];
    const float* y    = (const float*)d_in[1];
    const int*   rep  = (const int*)d_in[2];
    const float* ln_w = (const float*)d_in[3];
    const float* q_w  = (const float*)d_in[4];
    const float* q_b  = (const float*)d_in[5];
    const float* k_w  = (const float*)d_in[6];
    const float* k_b  = (const float*)d_in[7];
    const float* v_w  = (const float*)d_in[8];
    const float* v_b  = (const float*)d_in[9];
    float* out = (float*)d_out;

    cudaFuncSetAttribute(k_gemm_q,  cudaFuncAttributeMaxDynamicSharedMemorySize, SMEM_Q);
    cudaFuncSetAttribute(k_gemm_kv, cudaFuncAttributeMaxDynamicSharedMemorySize, SMEM_KV);

    k_mark<<<64, 1024>>>(rep);          // flags are 0 (BSS init / cleared by k_prep)
    k_scan<<<1, 1024>>>();
    k_prep<<<PREP_GRID, 256>>>(x, ln_w, q_w, k_w, v_w, rep);

    dim3 grid(HID / 128, NROWS / 128);  // (8, 512)
    k_gemm_q<<<grid, 256, SMEM_Q>>>(q_b, y);
    k_gemm_kv<<<grid, 256, SMEM_KV>>>(x, k_b, v_b, out);
}